// round 16
// baseline (speedup 1.0000x reference)
#include <cuda_runtime.h>
#include <math.h>

#define NPTS   8192
#define BATCH  2
#define TI     128                  // rows per block tile
#define TJ     1024                 // cols per block tile
#define IT     (NPTS / TI)          // 64 row tiles
#define JT     (NPTS / TJ)          // 8 col tiles
#define THREADS 256
#define IR     8                    // rows per thread (ty: 16 groups)
#define NPHASE 4                    // 4 phases x 256 cols
#define CPPH   8                    // col-pair iterations per phase
#define CRP    264                  // colred row pitch (even -> float2-safe)
#define FPSCALE 17592186044416.0    // 2^44 fixed-point scale
#define NGROUPS (IT * BATCH + JT * BATCH)   // 128 row + 16 col = 144

// Global min bits: [side][b][n]; side 0 = gt rows (dist1), 1 = pred cols (dist2).
__device__ unsigned int g_minbits[2 * BATCH * NPTS];
// Control block, zeroed by memset each run.
__device__ struct {
    unsigned long long acc;              // fixed-point sum
    unsigned int rowctr[IT * BATCH];     // 8 blocks per row group
    unsigned int colctr[JT * BATCH];     // 64 blocks per col group
    unsigned int gdone;                  // completed groups (target 144)
} g_ctl;

// ---- packed f32x2 helpers --------------------------------------------------
union f2u { unsigned long long u; float2 f; };
static __device__ __forceinline__ unsigned long long pack2(float lo, float hi) {
    f2u v; v.f = make_float2(lo, hi); return v.u;
}
static __device__ __forceinline__ unsigned long long fma2(
    unsigned long long a, unsigned long long b, unsigned long long c) {
    unsigned long long d;
    asm("fma.rn.f32x2 %0, %1, %2, %3;" : "=l"(d) : "l"(a), "l"(b), "l"(c));
    return d;
}
static __device__ __forceinline__ unsigned long long add2(
    unsigned long long a, unsigned long long b) {
    unsigned long long d;
    asm("add.rn.f32x2 %0, %1, %2;" : "=l"(d) : "l"(a), "l"(b));
    return d;
}
static __device__ __forceinline__ unsigned int enc_f(float f) {
    unsigned int u = __float_as_uint(f);
    return (u & 0x80000000u) ? ~u : (u | 0x80000000u);
}
static __device__ __forceinline__ float dec_f(unsigned int u) {
    u = (u & 0x80000000u) ? (u ^ 0x80000000u) : ~u;
    return __uint_as_float(u);
}
// acq_rel counter increment: release our prior writes, acquire others'.
static __device__ __forceinline__ unsigned int ctr_add_acqrel(
    unsigned int* p, unsigned int inc) {
    unsigned int old;
    asm volatile("atom.add.acq_rel.gpu.u32 %0, [%1], %2;"
                 : "=r"(old) : "l"(p), "r"(inc) : "memory");
    return old;
}

// Grid (IT, JT, BATCH). Tile: 128 gt-rows x 1024 pred-cols.
__global__ void __launch_bounds__(THREADS)
fused_kernel(const float* __restrict__ pred, const float* __restrict__ gt,
             float* __restrict__ out) {
    __shared__ float4 qrow[TI];          // (x, y, z, g2)              2 KB
    __shared__ float4 colA[TJ / 2];      // {-2x0,-2x1,-2y0,-2y1}      8 KB
    __shared__ float4 colB[TJ / 2];      // {-2z0,-2z1,  w0,  w1}      8 KB
    __shared__ float  colred[16][CRP];   // per-ty-group col mins    ~16.5 KB
    __shared__ int    s_flags;

    int it = blockIdx.x, jt = blockIdx.y, b = blockIdx.z;
    int tid = threadIdx.x;

    for (int i = tid; i < TI; i += THREADS) {
        const float* g = gt + (long)(b * NPTS + it * TI + i) * 3;
        float x = g[0], y = g[1], z = g[2];
        qrow[i] = make_float4(x, y, z, x * x + y * y + z * z);
    }
    for (int p = tid; p < TJ / 2; p += THREADS) {
        const float* q = pred + (long)(b * NPTS + jt * TJ + 2 * p) * 3;
        float x0 = q[0], y0 = q[1], z0 = q[2];
        float x1 = q[3], y1 = q[4], z1 = q[5];
        colA[p] = make_float4(-2.f * x0, -2.f * x1, -2.f * y0, -2.f * y1);
        colB[p] = make_float4(-2.f * z0, -2.f * z1,
                              x0 * x0 + y0 * y0 + z0 * z0,
                              x1 * x1 + y1 * y1 + z1 * z1);
    }
    __syncthreads();

    int ty = tid >> 4, tx = tid & 15;

    unsigned long long qxd[IR], qyd[IR], qzd[IR], g22[IR];
    float rowacc[IR];
#pragma unroll
    for (int r = 0; r < IR; r++) {
        float4 q = qrow[ty * IR + r];
        qxd[r] = pack2(q.x, q.x); qyd[r] = pack2(q.y, q.y);
        qzd[r] = pack2(q.z, q.z); g22[r] = pack2(q.w, q.w);
        rowacc[r] = 3.4e38f;
    }

    const ulonglong2* cA = (const ulonglong2*)colA;
    const ulonglong2* cB = (const ulonglong2*)colB;

    for (int phase = 0; phase < NPHASE; phase++) {
#pragma unroll 4
        for (int cp = 0; cp < CPPH; cp++) {
            int p = phase * 128 + cp * 16 + tx;   // lanes: consecutive 16B chunks
            ulonglong2 P0 = cA[p];
            ulonglong2 P1 = cB[p];
            float clo = 3.4e38f, chi = 3.4e38f;
#pragma unroll
            for (int r = 0; r < IR; r++) {
                unsigned long long t =
                    fma2(qxd[r], P0.x, fma2(qyd[r], P0.y, fma2(qzd[r], P1.x, P1.y)));
                f2u s; s.u = add2(t, g22[r]);
                float slo = s.f.x, shi = s.f.y;
                rowacc[r] = fminf(rowacc[r], fminf(slo, shi));
                clo = fminf(clo, slo);
                chi = fminf(chi, shi);
            }
            *(float2*)&colred[ty][2 * (cp * 16 + tx)] = make_float2(clo, chi);
        }
        __syncthreads();
        {
            int s0 = tid;                        // 0..255, one col per thread
            float m = colred[0][s0];
#pragma unroll
            for (int w = 1; w < 16; w++) m = fminf(m, colred[w][s0]);
            int col = jt * TJ + phase * 256 + s0;
            atomicMin(&g_minbits[(BATCH * NPTS) + (b << 13) + col], enc_f(m));
        }
        __syncthreads();
    }

    // Row mins: butterfly over the 16 tx lanes.
#pragma unroll
    for (int r = 0; r < IR; r++) {
        float v = rowacc[r];
        v = fminf(v, __shfl_xor_sync(0xffffffffu, v, 1));
        v = fminf(v, __shfl_xor_sync(0xffffffffu, v, 2));
        v = fminf(v, __shfl_xor_sync(0xffffffffu, v, 4));
        v = fminf(v, __shfl_xor_sync(0xffffffffu, v, 8));
        if (tx == 0)
            atomicMin(&g_minbits[(b << 13) + it * TI + ty * IR + r], enc_f(v));
    }

    // ---- Distributed reduction epilogue (no threadfence; acq_rel counters) --
    __syncthreads();   // HB: every thread's atomicMin precedes thread0's release
    if (tid == 0) {
        int f = 0;
        if (ctr_add_acqrel(&g_ctl.rowctr[it * BATCH + b], 1u) == JT - 1) f |= 1;
        if (ctr_add_acqrel(&g_ctl.colctr[jt * BATCH + b], 1u) == IT - 1) f |= 2;
        s_flags = f;
    }
    __syncthreads();
    int f = s_flags;
    if (f) {   // group-last: the group's mins are final (acquired above)
        float psum = 0.0f;
        if ((f & 1) && tid < TI)
            psum += sqrtf(fmaxf(dec_f(g_minbits[(b << 13) + it * TI + tid]), 0.f));
        if (f & 2)
            for (int c0 = tid; c0 < TJ; c0 += THREADS)
                psum += sqrtf(fmaxf(
                    dec_f(g_minbits[(BATCH * NPTS) + (b << 13) + jt * TJ + c0]), 0.f));
        float* sb = &colred[0][0];
        sb[tid] = psum;
        __syncthreads();
        for (int off = 128; off > 0; off >>= 1) {
            if (tid < off) sb[tid] += sb[tid + off];
            __syncthreads();
        }
        if (tid == 0) {
            atomicAdd(&g_ctl.acc, (unsigned long long)((double)sb[0] * FPSCALE));
            unsigned int inc = (unsigned int)((f & 1) + ((f >> 1) & 1));
            unsigned int od = ctr_add_acqrel(&g_ctl.gdone, inc);
            if (od + inc == NGROUPS) {   // final group completion
                unsigned long long acc =
                    *(volatile unsigned long long*)&g_ctl.acc;
                out[0] = (float)((double)acc / FPSCALE / (double)(BATCH * NPTS));
            }
        }
    }
}

extern "C" void kernel_launch(void* const* d_in, const int* in_sizes, int n_in,
                              void* d_out, int out_size) {
    const float* pred = (const float*)d_in[0];
    const float* gt   = (const float*)d_in[1];
    float* out = (float*)d_out;

    void* mb_ptr = 0; void* ctl_ptr = 0;
    cudaGetSymbolAddress(&mb_ptr, g_minbits);
    cudaGetSymbolAddress(&ctl_ptr, g_ctl);
    cudaMemsetAsync(mb_ptr, 0xFF, sizeof(unsigned int) * 2 * BATCH * NPTS);
    cudaMemsetAsync(ctl_ptr, 0, sizeof(g_ctl));

    dim3 grid(IT, JT, BATCH);
    fused_kernel<<<grid, THREADS>>>(pred, gt, out);
}

// round 17
// speedup vs baseline: 1.1490x; 1.1490x over previous
#include <cuda_runtime.h>
#include <math.h>

#define NPTS   8192
#define BATCH  2
#define TI     128                  // rows per block tile
#define TJ     1024                 // cols per block tile
#define IT     (NPTS / TI)          // 64 row tiles
#define JT     (NPTS / TJ)          // 8 col tiles
#define THREADS 256
#define IR     8                    // rows per thread (ty: 16 groups)
#define NPHASE 4                    // 4 phases x 256 cols
#define CPPH   8                    // col-pair iterations per phase
#define CRP    264                  // colred row pitch (even -> float2-safe)

// Global min bits: [side][b][n]; side 0 = gt rows (dist1), 1 = pred cols (dist2).
__device__ unsigned int g_minbits[2 * BATCH * NPTS];
__device__ float g_bsum[128];

// ---- packed f32x2 helpers --------------------------------------------------
union f2u { unsigned long long u; float2 f; };
static __device__ __forceinline__ unsigned long long pack2(float lo, float hi) {
    f2u v; v.f = make_float2(lo, hi); return v.u;
}
static __device__ __forceinline__ unsigned long long fma2(
    unsigned long long a, unsigned long long b, unsigned long long c) {
    unsigned long long d;
    asm("fma.rn.f32x2 %0, %1, %2, %3;" : "=l"(d) : "l"(a), "l"(b), "l"(c));
    return d;
}
static __device__ __forceinline__ unsigned long long add2(
    unsigned long long a, unsigned long long b) {
    unsigned long long d;
    asm("add.rn.f32x2 %0, %1, %2;" : "=l"(d) : "l"(a), "l"(b));
    return d;
}
static __device__ __forceinline__ unsigned int enc_f(float f) {
    unsigned int u = __float_as_uint(f);
    return (u & 0x80000000u) ? ~u : (u | 0x80000000u);
}
static __device__ __forceinline__ float dec_f(unsigned int u) {
    u = (u & 0x80000000u) ? (u ^ 0x80000000u) : ~u;
    return __uint_as_float(u);
}

// Grid (IT, JT, BATCH). Tile: 128 gt-rows x 1024 pred-cols.
// s_ij = g2_i + p2_j - 2<g_i,p_j>; row-min and col-min -> atomicMin epilogue.
__global__ void __launch_bounds__(THREADS)
fused_kernel(const float* __restrict__ pred, const float* __restrict__ gt) {
    __shared__ float4 qrow[TI];          // (x, y, z, g2)              2 KB
    __shared__ float4 colA[TJ / 2];      // {-2x0,-2x1,-2y0,-2y1}      8 KB
    __shared__ float4 colB[TJ / 2];      // {-2z0,-2z1,  w0,  w1}      8 KB
    __shared__ float  colred[16][CRP];   // per-ty-group col mins    ~16.5 KB

    int it = blockIdx.x, jt = blockIdx.y, b = blockIdx.z;
    int tid = threadIdx.x;

    for (int i = tid; i < TI; i += THREADS) {
        const float* g = gt + (long)(b * NPTS + it * TI + i) * 3;
        float x = g[0], y = g[1], z = g[2];
        qrow[i] = make_float4(x, y, z, x * x + y * y + z * z);
    }
    for (int p = tid; p < TJ / 2; p += THREADS) {
        const float* q = pred + (long)(b * NPTS + jt * TJ + 2 * p) * 3;
        float x0 = q[0], y0 = q[1], z0 = q[2];
        float x1 = q[3], y1 = q[4], z1 = q[5];
        colA[p] = make_float4(-2.f * x0, -2.f * x1, -2.f * y0, -2.f * y1);
        colB[p] = make_float4(-2.f * z0, -2.f * z1,
                              x0 * x0 + y0 * y0 + z0 * z0,
                              x1 * x1 + y1 * y1 + z1 * z1);
    }
    __syncthreads();

    int ty = tid >> 4, tx = tid & 15;

    unsigned long long qxd[IR], qyd[IR], qzd[IR], g22[IR];
    float rowacc[IR];
#pragma unroll
    for (int r = 0; r < IR; r++) {
        float4 q = qrow[ty * IR + r];
        qxd[r] = pack2(q.x, q.x); qyd[r] = pack2(q.y, q.y);
        qzd[r] = pack2(q.z, q.z); g22[r] = pack2(q.w, q.w);
        rowacc[r] = 3.4e38f;
    }

    const ulonglong2* cA = (const ulonglong2*)colA;
    const ulonglong2* cB = (const ulonglong2*)colB;

    for (int phase = 0; phase < NPHASE; phase++) {
#pragma unroll
        for (int cp = 0; cp < CPPH; cp++) {
            int p = phase * 128 + cp * 16 + tx;   // lanes: consecutive 16B chunks
            ulonglong2 P0 = cA[p];
            ulonglong2 P1 = cB[p];
            // Two independent col-accumulator chains (even/odd r) to halve
            // the serial FMNMX dependency per cp iteration.
            float cloA = 3.4e38f, chiA = 3.4e38f;
            float cloB = 3.4e38f, chiB = 3.4e38f;
#pragma unroll
            for (int r = 0; r < IR; r += 2) {
                unsigned long long tA =
                    fma2(qxd[r], P0.x, fma2(qyd[r], P0.y, fma2(qzd[r], P1.x, P1.y)));
                f2u sA; sA.u = add2(tA, g22[r]);
                rowacc[r] = fminf(rowacc[r], fminf(sA.f.x, sA.f.y));
                cloA = fminf(cloA, sA.f.x);
                chiA = fminf(chiA, sA.f.y);

                unsigned long long tB =
                    fma2(qxd[r + 1], P0.x,
                         fma2(qyd[r + 1], P0.y, fma2(qzd[r + 1], P1.x, P1.y)));
                f2u sB; sB.u = add2(tB, g22[r + 1]);
                rowacc[r + 1] = fminf(rowacc[r + 1], fminf(sB.f.x, sB.f.y));
                cloB = fminf(cloB, sB.f.x);
                chiB = fminf(chiB, sB.f.y);
            }
            float clo = fminf(cloA, cloB);
            float chi = fminf(chiA, chiB);
            *(float2*)&colred[ty][2 * (cp * 16 + tx)] = make_float2(clo, chi);
        }
        __syncthreads();
        // Flush this phase's 256 columns: min over 16 ty slices -> atomicMin.
        {
            int s0 = tid;                        // 0..255, one col per thread
            float m = colred[0][s0];
#pragma unroll
            for (int w = 1; w < 16; w++) m = fminf(m, colred[w][s0]);
            int col = jt * TJ + phase * 256 + s0;
            atomicMin(&g_minbits[(BATCH * NPTS) + (b << 13) + col], enc_f(m));
        }
        __syncthreads();
    }

    // Row mins: butterfly over the 16 tx lanes (masks stay inside halves).
#pragma unroll
    for (int r = 0; r < IR; r++) {
        float v = rowacc[r];
        v = fminf(v, __shfl_xor_sync(0xffffffffu, v, 1));
        v = fminf(v, __shfl_xor_sync(0xffffffffu, v, 2));
        v = fminf(v, __shfl_xor_sync(0xffffffffu, v, 4));
        v = fminf(v, __shfl_xor_sync(0xffffffffu, v, 8));
        if (tx == 0)
            atomicMin(&g_minbits[(b << 13) + it * TI + ty * IR + r], enc_f(v));
    }
}

// Stage 1: 128 blocks x 256 threads, one min-slot each -> 128 partial sums.
__global__ void __launch_bounds__(256)
reduce2_kernel() {
    int idx = blockIdx.x * 256 + threadIdx.x;   // < 32768
    float m = dec_f(g_minbits[idx]);
    float s = sqrtf(fmaxf(m, 0.0f));

    __shared__ float sb[256];
    sb[threadIdx.x] = s;
    __syncthreads();
    for (int off = 128; off > 0; off >>= 1) {
        if (threadIdx.x < off) sb[threadIdx.x] += sb[threadIdx.x + off];
        __syncthreads();
    }
    if (threadIdx.x == 0) g_bsum[blockIdx.x] = sb[0];
}

// Stage 2: one tiny block sums the 128 partials.
__global__ void __launch_bounds__(128)
reduce3_kernel(float* __restrict__ out) {
    __shared__ float sb[128];
    sb[threadIdx.x] = g_bsum[threadIdx.x];
    __syncthreads();
    for (int off = 64; off > 0; off >>= 1) {
        if (threadIdx.x < off) sb[threadIdx.x] += sb[threadIdx.x + off];
        __syncthreads();
    }
    if (threadIdx.x == 0) out[0] = sb[0] / (float)(BATCH * NPTS);
}

extern "C" void kernel_launch(void* const* d_in, const int* in_sizes, int n_in,
                              void* d_out, int out_size) {
    const float* pred = (const float*)d_in[0];
    const float* gt   = (const float*)d_in[1];
    float* out = (float*)d_out;

    void* mb_ptr = 0;
    cudaGetSymbolAddress(&mb_ptr, g_minbits);
    cudaMemsetAsync(mb_ptr, 0xFF, sizeof(unsigned int) * 2 * BATCH * NPTS);

    dim3 grid(IT, JT, BATCH);
    fused_kernel<<<grid, THREADS>>>(pred, gt);
    reduce2_kernel<<<128, 256>>>();
    reduce3_kernel<<<1, 128>>>(out);
}